// round 2
// baseline (speedup 1.0000x reference)
#include <cuda_runtime.h>
#include <cstdint>

#define N_NODES 100000
#define N_EDGES 1600000
#define DIM 64
#define HID 128

__device__ int g_idx_is64;

// ---------------------------------------------------------------------------
// Kernel 0: detect whether edge_index is int64 or int32.
// For int64 data (values < 2^31), every odd 32-bit word is 0.
// For int32 data, odd words are random node ids (~0 chance all 64 are zero).
// ---------------------------------------------------------------------------
__global__ void detect_kernel(const int* __restrict__ ei32) {
    int any = 0;
    #pragma unroll
    for (int i = 0; i < 64; i++) any |= ei32[2 * i + 1];
    g_idx_is64 = (any == 0) ? 1 : 0;
}

// ---------------------------------------------------------------------------
// Kernel 1: out = x  (agg initialized with self term, (1+eps)=1)
// ---------------------------------------------------------------------------
__global__ void init_kernel(const float4* __restrict__ x, float4* __restrict__ out) {
    int i = blockIdx.x * blockDim.x + threadIdx.x;
    if (i < N_NODES * DIM / 4) out[i] = x[i];
}

// ---------------------------------------------------------------------------
// Kernel 2: scatter-add. One thread = (edge, 16B chunk). 25.6M work items.
// Vector red.global.add.v4.f32 -> 1 L2 atomic op per 16 bytes.
// ---------------------------------------------------------------------------
__global__ void scatter_kernel(const float* __restrict__ x,
                               const void* __restrict__ ei_raw,
                               float* __restrict__ out) {
    int i = blockIdx.x * blockDim.x + threadIdx.x;
    if (i >= N_EDGES * (DIM / 4)) return;
    int e = i >> 4;        // edge id
    int c = i & 15;        // float4 chunk within the 64-float row

    unsigned int s, d;
    if (g_idx_is64) {
        const long long* ei = (const long long*)ei_raw;
        s = (unsigned int)ei[e];
        d = (unsigned int)ei[N_EDGES + e];
    } else {
        const int* ei = (const int*)ei_raw;
        s = (unsigned int)ei[e];
        d = (unsigned int)ei[N_EDGES + e];
    }
    if (s >= N_NODES || d >= N_NODES) return;  // safety: finite error beats a crash

    float4 v = __ldg(((const float4*)(x + (size_t)s * DIM)) + c);
    float* p = out + (size_t)d * DIM + c * 4;
    asm volatile("red.global.add.v4.f32 [%0], {%1, %2, %3, %4};"
                 :: "l"(p), "f"(v.x), "f"(v.y), "f"(v.z), "f"(v.w)
                 : "memory");
}

// ---------------------------------------------------------------------------
// Kernel 3: per-node MLP, in-place on out.
// Thread = node. W1 (64x128) + W2 (128x64) + biases in dynamic shared (~65KB).
// Row held in registers; weights read via broadcast LDS.128.
// Reads its own row fully before writing it back -> safe in-place.
// ---------------------------------------------------------------------------
__global__ __launch_bounds__(256, 1)
void mlp_kernel(float* __restrict__ buf,
                const float* __restrict__ W1, const float* __restrict__ b1,
                const float* __restrict__ W2, const float* __restrict__ b2) {
    extern __shared__ float smem[];
    float4* W1s = (float4*)smem;                  // 64*128 floats (k-major, j contiguous)
    float4* W2s = (float4*)(smem + DIM * HID);    // 128*64 floats (j-major, d contiguous)
    float*  b1s = smem + 2 * DIM * HID;           // 128
    float*  b2s = b1s + HID;                      // 64

    for (int i = threadIdx.x; i < DIM * HID; i += 256) {
        ((float*)W1s)[i] = W1[i];
        ((float*)W2s)[i] = W2[i];
    }
    for (int i = threadIdx.x; i < HID; i += 256) b1s[i] = b1[i];
    for (int i = threadIdx.x; i < DIM; i += 256) b2s[i] = b2[i];
    __syncthreads();

    int node = blockIdx.x * 256 + threadIdx.x;
    if (node >= N_NODES) return;

    // Load this node's aggregated row into registers.
    float xr[DIM];
    const float4* rp = (const float4*)(buf + (size_t)node * DIM);
    #pragma unroll
    for (int k4 = 0; k4 < DIM / 4; k4++) {
        float4 v = __ldg(rp + k4);
        xr[k4 * 4 + 0] = v.x; xr[k4 * 4 + 1] = v.y;
        xr[k4 * 4 + 2] = v.z; xr[k4 * 4 + 3] = v.w;
    }

    // y accumulators (second layer), init with b2.
    float4 y4[DIM / 4];
    #pragma unroll
    for (int d4 = 0; d4 < DIM / 4; d4++) y4[d4] = ((const float4*)b2s)[d4];

    // Stream over hidden units in groups of 4.
    #pragma unroll 1
    for (int j0 = 0; j0 < HID; j0 += 4) {
        float4 a = *(const float4*)(b1s + j0);
        #pragma unroll
        for (int k = 0; k < DIM; k++) {
            float4 w = W1s[k * (HID / 4) + (j0 >> 2)];
            a.x += xr[k] * w.x; a.y += xr[k] * w.y;
            a.z += xr[k] * w.z; a.w += xr[k] * w.w;
        }
        a.x = fmaxf(a.x, 0.f); a.y = fmaxf(a.y, 0.f);
        a.z = fmaxf(a.z, 0.f); a.w = fmaxf(a.w, 0.f);

        #pragma unroll
        for (int d4 = 0; d4 < DIM / 4; d4++) {
            float4 w0 = W2s[(j0 + 0) * (DIM / 4) + d4];
            float4 w1 = W2s[(j0 + 1) * (DIM / 4) + d4];
            float4 w2 = W2s[(j0 + 2) * (DIM / 4) + d4];
            float4 w3 = W2s[(j0 + 3) * (DIM / 4) + d4];
            y4[d4].x += a.x * w0.x; y4[d4].y += a.x * w0.y; y4[d4].z += a.x * w0.z; y4[d4].w += a.x * w0.w;
            y4[d4].x += a.y * w1.x; y4[d4].y += a.y * w1.y; y4[d4].z += a.y * w1.z; y4[d4].w += a.y * w1.w;
            y4[d4].x += a.z * w2.x; y4[d4].y += a.z * w2.y; y4[d4].z += a.z * w2.z; y4[d4].w += a.z * w2.w;
            y4[d4].x += a.w * w3.x; y4[d4].y += a.w * w3.y; y4[d4].z += a.w * w3.z; y4[d4].w += a.w * w3.w;
        }
    }

    float4* op = (float4*)(buf + (size_t)node * DIM);
    #pragma unroll
    for (int d4 = 0; d4 < DIM / 4; d4++) op[d4] = y4[d4];
}

// ---------------------------------------------------------------------------
// Launch
// ---------------------------------------------------------------------------
extern "C" void kernel_launch(void* const* d_in, const int* in_sizes, int n_in,
                              void* d_out, int out_size) {
    const float* x  = (const float*)d_in[0];
    const void*  ei = d_in[1];
    const float* W1 = (const float*)d_in[2];
    const float* b1 = (const float*)d_in[3];
    const float* W2 = (const float*)d_in[4];
    const float* b2 = (const float*)d_in[5];
    float* out = (float*)d_out;

    size_t smem_bytes = (2 * DIM * HID + HID + DIM) * sizeof(float);
    cudaFuncSetAttribute(mlp_kernel, cudaFuncAttributeMaxDynamicSharedMemorySize,
                         (int)smem_bytes);

    // 0) detect index dtype (int32 vs int64)
    detect_kernel<<<1, 1>>>((const int*)ei);

    // 1) out = x
    {
        int n = N_NODES * DIM / 4;
        init_kernel<<<(n + 255) / 256, 256>>>((const float4*)x, (float4*)out);
    }
    // 2) scatter-add neighbors
    {
        int n = N_EDGES * (DIM / 4);
        scatter_kernel<<<(n + 255) / 256, 256>>>(x, ei, out);
    }
    // 3) MLP in-place
    {
        int blocks = (N_NODES + 255) / 256;
        mlp_kernel<<<blocks, 256, smem_bytes>>>(out, W1, b1, W2, b2);
    }
}

// round 3
// speedup vs baseline: 1.0958x; 1.0958x over previous
#include <cuda_runtime.h>
#include <cstdint>

#define N_NODES 100000
#define N_EDGES 1600000
#define DIM 64
#define HID 128

#define TILE_N 128
#define XT_STRIDE 132   // padded row stride (floats) for transposed tiles

__device__ int g_idx_is64;

// ---------------------------------------------------------------------------
// f32x2 packed-math helpers (SASS FFMA2 path, PTX-only)
// ---------------------------------------------------------------------------
__device__ __forceinline__ unsigned long long splat2(float v) {
    unsigned long long r;
    asm("mov.b64 %0, {%1, %1};" : "=l"(r) : "f"(v));
    return r;
}
__device__ __forceinline__ void ffma2(unsigned long long& d,
                                      unsigned long long a, unsigned long long b) {
    asm("fma.rn.f32x2 %0, %1, %2, %0;" : "+l"(d) : "l"(a), "l"(b));
}
__device__ __forceinline__ void unpack2(unsigned long long v, float& lo, float& hi) {
    asm("mov.b64 {%0, %1}, %2;" : "=f"(lo), "=f"(hi) : "l"(v));
}

// ---------------------------------------------------------------------------
// Kernel 0: detect whether edge_index is int64 or int32.
// ---------------------------------------------------------------------------
__global__ void detect_kernel(const int* __restrict__ ei32) {
    int any = 0;
    #pragma unroll
    for (int i = 0; i < 64; i++) any |= ei32[2 * i + 1];
    g_idx_is64 = (any == 0) ? 1 : 0;
}

// ---------------------------------------------------------------------------
// Kernel 1: out = x
// ---------------------------------------------------------------------------
__global__ void init_kernel(const float4* __restrict__ x, float4* __restrict__ out) {
    int i = blockIdx.x * blockDim.x + threadIdx.x;
    if (i < N_NODES * DIM / 4) out[i] = x[i];
}

// ---------------------------------------------------------------------------
// Kernel 2: scatter-add (L2-atomic bound, ~at LTS cap)
// ---------------------------------------------------------------------------
__global__ void scatter_kernel(const float* __restrict__ x,
                               const void* __restrict__ ei_raw,
                               float* __restrict__ out) {
    int i = blockIdx.x * blockDim.x + threadIdx.x;
    if (i >= N_EDGES * (DIM / 4)) return;
    int e = i >> 4;
    int c = i & 15;

    unsigned int s, d;
    if (g_idx_is64) {
        const long long* ei = (const long long*)ei_raw;
        s = (unsigned int)ei[e];
        d = (unsigned int)ei[N_EDGES + e];
    } else {
        const int* ei = (const int*)ei_raw;
        s = (unsigned int)ei[e];
        d = (unsigned int)ei[N_EDGES + e];
    }
    if (s >= N_NODES || d >= N_NODES) return;

    float4 v = __ldg(((const float4*)(x + (size_t)s * DIM)) + c);
    float* p = out + (size_t)d * DIM + c * 4;
    asm volatile("red.global.add.v4.f32 [%0], {%1, %2, %3, %4};"
                 :: "l"(p), "f"(v.x), "f"(v.y), "f"(v.z), "f"(v.w)
                 : "memory");
}

// ---------------------------------------------------------------------------
// Kernel 3: tiled MLP with f32x2 packed FMAs.
// Block = 128 nodes, 256 threads (16 x 16 thread grid).
// x tile & h tile stored TRANSPOSED ([k][node], stride 132) so the node-pair
// packed a-fragments load directly as ulonglong2 (no pack instructions).
// ---------------------------------------------------------------------------
__global__ __launch_bounds__(256, 1)
void mlp_kernel(float* __restrict__ buf,
                const float* __restrict__ W1, const float* __restrict__ b1,
                const float* __restrict__ W2, const float* __restrict__ b2) {
    extern __shared__ float smem[];
    float* x_t = smem;                          // [64][132]
    float* h_t = x_t + DIM * XT_STRIDE;         // [128][132]
    float* W1s = h_t + HID * XT_STRIDE;         // [64][128] k-major
    float* W2s = W1s + DIM * HID;               // [128][64] j-major
    float* b1s = W2s + HID * DIM;               // [128]
    float* b2s = b1s + HID;                     // [64]

    int tid = threadIdx.x;
    int base = blockIdx.x * TILE_N;

    // --- load weights + biases ---
    for (int i = tid; i < DIM * HID; i += 256) {
        W1s[i] = W1[i];
        W2s[i] = W2[i];
    }
    if (tid < HID) b1s[tid] = b1[tid];
    if (tid < DIM) b2s[tid] = b2[tid];

    // --- load x tile, transposed ---
    for (int i = tid; i < TILE_N * (DIM / 4); i += 256) {
        int row = i >> 4;          // node within tile
        int c4  = i & 15;          // float4 chunk of the 64-dim row
        int node = base + row;
        float4 v = (node < N_NODES)
                       ? __ldg(((const float4*)(buf + (size_t)node * DIM)) + c4)
                       : make_float4(0.f, 0.f, 0.f, 0.f);
        x_t[(4 * c4 + 0) * XT_STRIDE + row] = v.x;
        x_t[(4 * c4 + 1) * XT_STRIDE + row] = v.y;
        x_t[(4 * c4 + 2) * XT_STRIDE + row] = v.z;
        x_t[(4 * c4 + 3) * XT_STRIDE + row] = v.w;
    }
    __syncthreads();

    int tx = tid & 15, ty = tid >> 4;
    int n0 = ty * 8;       // 8 nodes per thread
    int j0 = tx * 8;       // 8 hidden units per thread (layer 1)

    // ===================== Layer 1: h = relu(x @ W1 + b1) =====================
    unsigned long long acc[4][8];   // [node-pair][hidden]
    #pragma unroll
    for (int np = 0; np < 4; np++)
        #pragma unroll
        for (int j = 0; j < 8; j++) acc[np][j] = 0ull;

    #pragma unroll 4
    for (int k = 0; k < DIM; k++) {
        const ulonglong2* ap = (const ulonglong2*)(x_t + k * XT_STRIDE + n0);
        ulonglong2 a01 = ap[0];
        ulonglong2 a23 = ap[1];
        unsigned long long a2[4] = {a01.x, a01.y, a23.x, a23.y};

        float4 bv0 = *(const float4*)(W1s + k * HID + j0);
        float4 bv1 = *(const float4*)(W1s + k * HID + j0 + 4);
        unsigned long long bs[8] = {
            splat2(bv0.x), splat2(bv0.y), splat2(bv0.z), splat2(bv0.w),
            splat2(bv1.x), splat2(bv1.y), splat2(bv1.z), splat2(bv1.w)};

        #pragma unroll
        for (int np = 0; np < 4; np++)
            #pragma unroll
            for (int j = 0; j < 8; j++) ffma2(acc[np][j], a2[np], bs[j]);
    }

    // epilogue: bias + relu, store transposed h tile
    #pragma unroll
    for (int j = 0; j < 8; j++) {
        float hb = b1s[j0 + j];
        float h[8];
        #pragma unroll
        for (int np = 0; np < 4; np++) {
            float lo, hi;
            unpack2(acc[np][j], lo, hi);
            h[2 * np + 0] = fmaxf(lo + hb, 0.f);
            h[2 * np + 1] = fmaxf(hi + hb, 0.f);
        }
        float* hp = h_t + (j0 + j) * XT_STRIDE + n0;
        *(float4*)(hp)     = make_float4(h[0], h[1], h[2], h[3]);
        *(float4*)(hp + 4) = make_float4(h[4], h[5], h[6], h[7]);
    }
    __syncthreads();

    // ===================== Layer 2: y = h @ W2 + b2 =====================
    int d0 = tx * 4;       // 4 output dims per thread
    unsigned long long acc2[4][4];
    #pragma unroll
    for (int np = 0; np < 4; np++)
        #pragma unroll
        for (int d = 0; d < 4; d++) acc2[np][d] = 0ull;

    #pragma unroll 4
    for (int k = 0; k < HID; k++) {
        const ulonglong2* ap = (const ulonglong2*)(h_t + k * XT_STRIDE + n0);
        ulonglong2 a01 = ap[0];
        ulonglong2 a23 = ap[1];
        unsigned long long a2[4] = {a01.x, a01.y, a23.x, a23.y};

        float4 bv = *(const float4*)(W2s + k * DIM + d0);
        unsigned long long bs[4] = {splat2(bv.x), splat2(bv.y),
                                    splat2(bv.z), splat2(bv.w)};

        #pragma unroll
        for (int np = 0; np < 4; np++)
            #pragma unroll
            for (int d = 0; d < 4; d++) ffma2(acc2[np][d], a2[np], bs[d]);
    }

    // epilogue: bias, store to global (in-place on buf; x tile fully consumed)
    float bb[4] = {b2s[d0], b2s[d0 + 1], b2s[d0 + 2], b2s[d0 + 3]};
    #pragma unroll
    for (int np = 0; np < 4; np++) {
        float lo[4], hi[4];
        #pragma unroll
        for (int d = 0; d < 4; d++) unpack2(acc2[np][d], lo[d], hi[d]);
        int nA = base + n0 + 2 * np;
        int nB = nA + 1;
        if (nA < N_NODES)
            *(float4*)(buf + (size_t)nA * DIM + d0) =
                make_float4(lo[0] + bb[0], lo[1] + bb[1], lo[2] + bb[2], lo[3] + bb[3]);
        if (nB < N_NODES)
            *(float4*)(buf + (size_t)nB * DIM + d0) =
                make_float4(hi[0] + bb[0], hi[1] + bb[1], hi[2] + bb[2], hi[3] + bb[3]);
    }
}

// ---------------------------------------------------------------------------
// Launch
// ---------------------------------------------------------------------------
extern "C" void kernel_launch(void* const* d_in, const int* in_sizes, int n_in,
                              void* d_out, int out_size) {
    const float* x  = (const float*)d_in[0];
    const void*  ei = d_in[1];
    const float* W1 = (const float*)d_in[2];
    const float* b1 = (const float*)d_in[3];
    const float* W2 = (const float*)d_in[4];
    const float* b2 = (const float*)d_in[5];
    float* out = (float*)d_out;

    size_t smem_bytes =
        (DIM * XT_STRIDE + HID * XT_STRIDE + 2 * DIM * HID + HID + DIM) * sizeof(float);
    cudaFuncSetAttribute(mlp_kernel, cudaFuncAttributeMaxDynamicSharedMemorySize,
                         (int)smem_bytes);

    // 0) detect index dtype
    detect_kernel<<<1, 1>>>((const int*)ei);

    // 1) out = x
    {
        int n = N_NODES * DIM / 4;
        init_kernel<<<(n + 255) / 256, 256>>>((const float4*)x, (float4*)out);
    }
    // 2) scatter-add neighbors
    {
        int n = N_EDGES * (DIM / 4);
        scatter_kernel<<<(n + 255) / 256, 256>>>(x, ei, out);
    }
    // 3) tiled MLP in-place
    {
        int blocks = (N_NODES + TILE_N - 1) / TILE_N;
        mlp_kernel<<<blocks, 256, smem_bytes>>>(out, W1, b1, W2, b2);
    }
}

// round 5
// speedup vs baseline: 1.2047x; 1.0993x over previous
#include <cuda_runtime.h>
#include <cstdint>

#define N_NODES 100000
#define N_EDGES 1600000
#define DIM 64
#define HID 128
#define TILE_M 128

// tcgen05 is arch-SPECIFIC: only emit it in the sm_103a/sm_100a device pass.
// The plain compute_103 PTX pass compiles an empty kernel body (never executed;
// the exact-match sm_103a cubin is loaded at runtime).
#if defined(__CUDA_ARCH_FEAT_SM103_ALL) || defined(__CUDA_ARCH_FEAT_SM100_ALL) || \
    defined(__CUDA_ARCH_FEAT_SM101_ALL)
#define HAS_TCGEN05 1
#else
#define HAS_TCGEN05 0
#endif

__device__ int g_idx_is64;

// ---------------------------------------------------------------------------
// PTX helpers
// ---------------------------------------------------------------------------
__device__ __forceinline__ uint32_t smem_u32(const void* p) {
    uint32_t a;
    asm("{ .reg .u64 t; cvta.to.shared.u64 t, %1; cvt.u32.u64 %0, t; }" : "=r"(a) : "l"(p));
    return a;
}
__device__ __forceinline__ uint32_t elect_one() {
    uint32_t p;
    asm volatile("{ .reg .pred p; elect.sync _|p, 0xFFFFFFFF; selp.b32 %0, 1, 0, p; }" : "=r"(p));
    return p;
}
__device__ __forceinline__ uint32_t sw128(uint32_t b) { return b ^ ((b >> 3) & 0x70); }
__device__ __forceinline__ uint32_t cvt_tf32(float f) {
    uint32_t r;
    asm("cvt.rna.tf32.f32 %0, %1;" : "=r"(r) : "f"(f));
    return r;
}
// SW128 K-major descriptor: layout=2, version=1, SBO=64 (1024B / 8-row group), LBO=1
__device__ __forceinline__ uint64_t make_desc(uint32_t addr) {
    return (uint64_t(2) << 61) | (uint64_t(1) << 46) | (uint64_t(64) << 32) |
           (uint64_t(1) << 16) | ((uint64_t)(addr >> 4) & 0x3FFF);
}

#define MBAR_INIT(a, c) asm volatile("mbarrier.init.shared.b64 [%0], %1;" :: "r"(a), "r"(c) : "memory")
#define MBAR_INVAL(a)   asm volatile("mbarrier.inval.shared.b64 [%0];" :: "r"(a) : "memory")
#define MBAR_WAIT(a, ph) do {                                                     \
    uint32_t _m = (a), _p = (ph), _d;                                             \
    asm volatile("{ .reg .pred p; mbarrier.try_wait.parity.acquire.cta.shared::cta.b64 p, [%1], %2; selp.b32 %0,1,0,p; }" \
                 : "=r"(_d) : "r"(_m), "r"(_p) : "memory");                       \
    if (!_d) {                                                                    \
        asm volatile("{ .reg .pred P1; WL%=: mbarrier.try_wait.parity.acquire.cta.shared::cta.b64 P1, [%0], %1, 0x989680;" \
                     " @P1 bra.uni WD%=; bra.uni WL%=; WD%=: }"                   \
                     :: "r"(_m), "r"(_p) : "memory");                             \
    } } while (0)

#if HAS_TCGEN05
#define TC_ALLOC(sa, n)   asm volatile("tcgen05.alloc.cta_group::1.sync.aligned.shared::cta.b32 [%0], %1;" :: "r"(sa), "r"(n) : "memory")
#define TC_DEALLOC(t, n)  asm volatile("tcgen05.dealloc.cta_group::1.sync.aligned.b32 %0, %1;" :: "r"(t), "r"(n))
#define TC_RELINQ()       asm volatile("tcgen05.relinquish_alloc_permit.cta_group::1.sync.aligned;")
#define TC_COMMIT(mb)     asm volatile("tcgen05.commit.cta_group::1.mbarrier::arrive::one.shared::cluster.b64 [%0];" :: "r"(mb) : "memory")
#define TC_WAIT_LD()      asm volatile("tcgen05.wait::ld.sync.aligned;" ::: "memory")
#define TC_WAIT_ST()      asm volatile("tcgen05.wait::st.sync.aligned;" ::: "memory")
#define TC_FENCE_BEFORE() asm volatile("tcgen05.fence::before_thread_sync;" ::: "memory")
#define TC_FENCE_AFTER()  asm volatile("tcgen05.fence::after_thread_sync;" ::: "memory")
#define FENCE_ASYNC()     asm volatile("fence.proxy.async.shared::cta;" ::: "memory")

#define LDTM_X32(r, a)                                                              \
    asm volatile("tcgen05.ld.sync.aligned.32x32b.x32.b32 "                          \
        "{%0,%1,%2,%3,%4,%5,%6,%7,%8,%9,%10,%11,%12,%13,%14,%15,"                   \
        "%16,%17,%18,%19,%20,%21,%22,%23,%24,%25,%26,%27,%28,%29,%30,%31}, [%32];"  \
        : "=r"((r)[0]),"=r"((r)[1]),"=r"((r)[2]),"=r"((r)[3]),"=r"((r)[4]),"=r"((r)[5]),"=r"((r)[6]),"=r"((r)[7]), \
          "=r"((r)[8]),"=r"((r)[9]),"=r"((r)[10]),"=r"((r)[11]),"=r"((r)[12]),"=r"((r)[13]),"=r"((r)[14]),"=r"((r)[15]), \
          "=r"((r)[16]),"=r"((r)[17]),"=r"((r)[18]),"=r"((r)[19]),"=r"((r)[20]),"=r"((r)[21]),"=r"((r)[22]),"=r"((r)[23]), \
          "=r"((r)[24]),"=r"((r)[25]),"=r"((r)[26]),"=r"((r)[27]),"=r"((r)[28]),"=r"((r)[29]),"=r"((r)[30]),"=r"((r)[31]) \
        : "r"(a))

#define STTM_X32(a, r)                                                              \
    asm volatile("tcgen05.st.sync.aligned.32x32b.x32.b32 [%0], "                    \
        "{%1,%2,%3,%4,%5,%6,%7,%8,%9,%10,%11,%12,%13,%14,%15,%16,"                  \
        "%17,%18,%19,%20,%21,%22,%23,%24,%25,%26,%27,%28,%29,%30,%31,%32};"         \
        :: "r"(a),                                                                  \
           "r"((r)[0]),"r"((r)[1]),"r"((r)[2]),"r"((r)[3]),"r"((r)[4]),"r"((r)[5]),"r"((r)[6]),"r"((r)[7]), \
           "r"((r)[8]),"r"((r)[9]),"r"((r)[10]),"r"((r)[11]),"r"((r)[12]),"r"((r)[13]),"r"((r)[14]),"r"((r)[15]), \
           "r"((r)[16]),"r"((r)[17]),"r"((r)[18]),"r"((r)[19]),"r"((r)[20]),"r"((r)[21]),"r"((r)[22]),"r"((r)[23]), \
           "r"((r)[24]),"r"((r)[25]),"r"((r)[26]),"r"((r)[27]),"r"((r)[28]),"r"((r)[29]),"r"((r)[30]),"r"((r)[31]) \
        : "memory")

__device__ __forceinline__ void mma_tf32_ss(uint32_t d, uint64_t a, uint64_t b,
                                            uint32_t idesc, bool acc) {
    uint32_t e = acc ? 1u : 0u;
    asm volatile("{ .reg .pred p; setp.ne.u32 p, %4, 0;"
                 " tcgen05.mma.cta_group::1.kind::tf32 [%0], %1, %2, %3, p; }"
                 :: "r"(d), "l"(a), "l"(b), "r"(idesc), "r"(e) : "memory");
}
__device__ __forceinline__ void mma_tf32_ts(uint32_t d, uint32_t a, uint64_t b,
                                            uint32_t idesc, bool acc) {
    uint32_t e = acc ? 1u : 0u;
    asm volatile("{ .reg .pred p; setp.ne.u32 p, %4, 0;"
                 " tcgen05.mma.cta_group::1.kind::tf32 [%0], [%1], %2, %3, p; }"
                 :: "r"(d), "r"(a), "l"(b), "r"(idesc), "r"(e) : "memory");
}
#endif  // HAS_TCGEN05

// ---------------------------------------------------------------------------
// Kernel 0: detect int32 vs int64 edge index
// ---------------------------------------------------------------------------
__global__ void detect_kernel(const int* __restrict__ ei32) {
    int any = 0;
    #pragma unroll
    for (int i = 0; i < 64; i++) any |= ei32[2 * i + 1];
    g_idx_is64 = (any == 0) ? 1 : 0;
}

// ---------------------------------------------------------------------------
// Kernel 1: out = x
// ---------------------------------------------------------------------------
__global__ void init_kernel(const float4* __restrict__ x, float4* __restrict__ out) {
    int i = blockIdx.x * blockDim.x + threadIdx.x;
    if (i < N_NODES * DIM / 4) out[i] = x[i];
}

// ---------------------------------------------------------------------------
// Kernel 2: scatter-add (L2-atomic bound, at LTS cap)
// ---------------------------------------------------------------------------
__global__ void scatter_kernel(const float* __restrict__ x,
                               const void* __restrict__ ei_raw,
                               float* __restrict__ out) {
    int i = blockIdx.x * blockDim.x + threadIdx.x;
    if (i >= N_EDGES * (DIM / 4)) return;
    int e = i >> 4;
    int c = i & 15;

    unsigned int s, d;
    if (g_idx_is64) {
        const long long* ei = (const long long*)ei_raw;
        s = (unsigned int)ei[e];
        d = (unsigned int)ei[N_EDGES + e];
    } else {
        const int* ei = (const int*)ei_raw;
        s = (unsigned int)ei[e];
        d = (unsigned int)ei[N_EDGES + e];
    }
    if (s >= N_NODES || d >= N_NODES) return;

    float4 v = __ldg(((const float4*)(x + (size_t)s * DIM)) + c);
    float* p = out + (size_t)d * DIM + c * 4;
    asm volatile("red.global.add.v4.f32 [%0], {%1, %2, %3, %4};"
                 :: "l"(p), "f"(v.x), "f"(v.y), "f"(v.z), "f"(v.w)
                 : "memory");
}

// ---------------------------------------------------------------------------
// Kernel 3: MLP via tcgen05 tf32 MMA. CTA = 128 nodes, 128 threads.
// Layer1: SS (A=x smem, B=W1^T smem), M=128 N=128 K=64  -> D1 (TMEM 0..127)
// Epilogue1: LDTM D1, +b1, relu, cvt tf32, STTM -> A2 (TMEM 128..255)
// Layer2: TS (A=A2 TMEM, B=W2^T smem), M=128 N=64 K=128 -> D2 (TMEM 0..63)
// Epilogue2: LDTM D2, +b2, STG.128 in place.
// ---------------------------------------------------------------------------
#define SM_TMEM  0
#define SM_MBAR  8
#define SM_X     1024
#define SM_W1    (SM_X + 32768)
#define SM_W2    (SM_W1 + 32768)
#define SM_B1    (SM_W2 + 32768)
#define SM_B2    (SM_B1 + 512)
#define SM_TOTAL (SM_B2 + 512)

#define T_D1   0
#define T_A2   128
#define T_D2   0
#define T_COLS 256

// idesc: dtype=F32(1<<4), atype=btype=TF32(2), N>>3 at 17, M>>4 at 24
#define IDESC1 ((1u << 4) | (2u << 7) | (2u << 10) | ((HID / 8) << 17) | ((TILE_M / 16) << 24))
#define IDESC2 ((1u << 4) | (2u << 7) | (2u << 10) | ((DIM / 8) << 17) | ((TILE_M / 16) << 24))

__global__ __launch_bounds__(128, 1)
void mlp_tc_kernel(float* __restrict__ buf,
                   const float* __restrict__ W1, const float* __restrict__ b1,
                   const float* __restrict__ W2, const float* __restrict__ b2) {
#if HAS_TCGEN05
    extern __shared__ char smem[];
    uint32_t sb = smem_u32(smem);
    int tid = threadIdx.x;
    int wid = tid >> 5;
    int lid = tid & 31;
    int base = blockIdx.x * TILE_M;

    // TMEM alloc (warp 0)
    if (wid == 0) {
        TC_ALLOC(sb + SM_TMEM, T_COLS);
        TC_RELINQ();
    }
    __syncthreads();
    uint32_t tmem;
    asm volatile("ld.shared.b32 %0, [%1];" : "=r"(tmem) : "r"(sb + SM_TMEM));

    // --- x tile [row=node 0..127][col=k 0..63], blocked SW128 atoms (16 x 2) ---
    for (int idx = tid; idx < TILE_M * DIM; idx += 128) {
        int row = idx >> 6, col = idx & 63;
        int node = base + row;
        float v = (node < N_NODES) ? __ldg(buf + (size_t)node * DIM + col) : 0.f;
        uint32_t byte = ((row >> 3) + (col >> 5) * 16) * 1024 + (row & 7) * 128 + (col & 31) * 4;
        *(uint32_t*)(smem + SM_X + sw128(byte)) = cvt_tf32(v);
    }
    // --- W1^T tile [row=j 0..127][col=k 0..63] ---
    for (int idx = tid; idx < HID * DIM; idx += 128) {
        int j = idx >> 6, k = idx & 63;
        float v = __ldg(W1 + k * HID + j);
        uint32_t byte = ((j >> 3) + (k >> 5) * 16) * 1024 + (j & 7) * 128 + (k & 31) * 4;
        *(uint32_t*)(smem + SM_W1 + sw128(byte)) = cvt_tf32(v);
    }
    // --- W2^T tile [row=d 0..63][col=k 0..127], atoms (8 x 4) ---
    for (int idx = tid; idx < DIM * HID; idx += 128) {
        int d = idx >> 7, k = idx & 127;
        float v = __ldg(W2 + k * DIM + d);
        uint32_t byte = ((d >> 3) + (k >> 5) * 8) * 1024 + (d & 7) * 128 + (k & 31) * 4;
        *(uint32_t*)(smem + SM_W2 + sw128(byte)) = cvt_tf32(v);
    }
    if (tid < HID) ((float*)(smem + SM_B1))[tid] = b1[tid];
    if (tid < DIM) ((float*)(smem + SM_B2))[tid] = b2[tid];

    if (wid == 0 && elect_one()) MBAR_INIT(sb + SM_MBAR, 1);
    FENCE_ASYNC();
    __syncthreads();

    // ===== Layer 1: 8 SS MMAs (K=8 tf32 each) =====
    if (wid == 0) {
        TC_FENCE_AFTER();
        if (elect_one()) {
            uint64_t ad = make_desc(sb + SM_X);
            uint64_t bd = make_desc(sb + SM_W1);
            #pragma unroll
            for (int s = 0; s < 8; s++) {
                uint64_t off = (uint64_t)((s >> 2) * 1024 + (s & 3) * 2);
                mma_tf32_ss(tmem + T_D1, ad + off, bd + off, IDESC1, s > 0);
            }
            TC_COMMIT(sb + SM_MBAR);
        }
    }
    __syncthreads();
    MBAR_WAIT(sb + SM_MBAR, 0);
    TC_FENCE_AFTER();

    // ===== Epilogue 1: +b1, relu, cvt tf32, -> A2 =====
    {
        uint32_t woff = (uint32_t)wid << 21;
        const float* b1s = (const float*)(smem + SM_B1);
        #pragma unroll
        for (int c0 = 0; c0 < HID; c0 += 32) {
            uint32_t r[32];
            LDTM_X32(r, tmem + woff + T_D1 + c0);
            TC_WAIT_LD();
            #pragma unroll
            for (int i = 0; i < 32; i++) {
                float f = __uint_as_float(r[i]) + b1s[c0 + i];
                r[i] = cvt_tf32(fmaxf(f, 0.f));
            }
            STTM_X32(tmem + woff + T_A2 + c0, r);
        }
        TC_WAIT_ST();
    }
    TC_FENCE_BEFORE();
    __syncthreads();

    // ===== Layer 2: 16 TS MMAs (A in TMEM) =====
    if (wid == 0) {
        TC_FENCE_AFTER();
        if (elect_one()) {
            uint64_t bd = make_desc(sb + SM_W2);
            #pragma unroll
            for (int s = 0; s < 16; s++) {
                uint64_t off = (uint64_t)((s >> 2) * 512 + (s & 3) * 2);
                mma_tf32_ts(tmem + T_D2, tmem + T_A2 + s * 8, bd + off, IDESC2, s > 0);
            }
            TC_COMMIT(sb + SM_MBAR);
        }
    }
    __syncthreads();
    MBAR_WAIT(sb + SM_MBAR, 1);
    TC_FENCE_AFTER();

    // ===== Epilogue 2: +b2, store =====
    {
        uint32_t woff = (uint32_t)wid << 21;
        const float* b2s = (const float*)(smem + SM_B2);
        int node = base + wid * 32 + lid;
        #pragma unroll
        for (int c0 = 0; c0 < DIM; c0 += 32) {
            uint32_t r[32];
            LDTM_X32(r, tmem + woff + T_D2 + c0);
            TC_WAIT_LD();
            if (node < N_NODES) {
                float* op = buf + (size_t)node * DIM + c0;
                #pragma unroll
                for (int g = 0; g < 8; g++) {
                    float4 v;
                    v.x = __uint_as_float(r[4 * g + 0]) + b2s[c0 + 4 * g + 0];
                    v.y = __uint_as_float(r[4 * g + 1]) + b2s[c0 + 4 * g + 1];
                    v.z = __uint_as_float(r[4 * g + 2]) + b2s[c0 + 4 * g + 2];
                    v.w = __uint_as_float(r[4 * g + 3]) + b2s[c0 + 4 * g + 3];
                    *(float4*)(op + 4 * g) = v;
                }
            }
        }
    }

    __syncthreads();
    if (wid == 0) {
        if (elect_one()) MBAR_INVAL(sb + SM_MBAR);
        TC_DEALLOC(tmem, T_COLS);
    }
#endif  // HAS_TCGEN05
}

// ---------------------------------------------------------------------------
// Launch
// ---------------------------------------------------------------------------
extern "C" void kernel_launch(void* const* d_in, const int* in_sizes, int n_in,
                              void* d_out, int out_size) {
    const float* x  = (const float*)d_in[0];
    const void*  ei = d_in[1];
    const float* W1 = (const float*)d_in[2];
    const float* b1 = (const float*)d_in[3];
    const float* W2 = (const float*)d_in[4];
    const float* b2 = (const float*)d_in[5];
    float* out = (float*)d_out;

    cudaFuncSetAttribute(mlp_tc_kernel, cudaFuncAttributeMaxDynamicSharedMemorySize,
                         SM_TOTAL);

    detect_kernel<<<1, 1>>>((const int*)ei);
    {
        int n = N_NODES * DIM / 4;
        init_kernel<<<(n + 255) / 256, 256>>>((const float4*)x, (float4*)out);
    }
    {
        int n = N_EDGES * (DIM / 4);
        scatter_kernel<<<(n + 255) / 256, 256>>>(x, ei, out);
    }
    {
        int blocks = (N_NODES + TILE_M - 1) / TILE_M;
        mlp_tc_kernel<<<blocks, 128, SM_TOTAL>>>(out, W1, b1, W2, b2);
    }
}

// round 6
// speedup vs baseline: 1.8038x; 1.4973x over previous
#include <cuda_runtime.h>
#include <cstdint>

#define N_NODES 100000
#define N_EDGES 1600000
#define DIM 64
#define HID 128
#define TILE_M 128
#define NT 782
#define TILES_PER_CTA 3
#define MLP_GRID 261

#if defined(__CUDA_ARCH_FEAT_SM103_ALL) || defined(__CUDA_ARCH_FEAT_SM100_ALL) || \
    defined(__CUDA_ARCH_FEAT_SM101_ALL)
#define HAS_TCGEN05 1
#else
#define HAS_TCGEN05 0
#endif

__device__ int g_idx_is64;
__device__ uint32_t g_w1t[DIM * HID];
__device__ uint32_t g_w2t[HID * DIM];

__device__ __forceinline__ uint32_t smem_u32(const void* p) {
    uint32_t a;
    asm("{ .reg .u64 t; cvta.to.shared.u64 t, %1; cvt.u32.u64 %0, t; }" : "=r"(a) : "l"(p));
    return a;
}
__device__ __forceinline__ uint32_t elect_one() {
    uint32_t p;
    asm volatile("{ .reg .pred p; elect.sync _|p, 0xFFFFFFFF; selp.b32 %0, 1, 0, p; }" : "=r"(p));
    return p;
}
__device__ __forceinline__ uint32_t sw128(uint32_t b) { return b ^ ((b >> 3) & 0x70); }
__device__ __forceinline__ uint32_t cvt_tf32(float f) {
    uint32_t r;
    asm("cvt.rna.tf32.f32 %0, %1;" : "=r"(r) : "f"(f));
    return r;
}
__device__ __forceinline__ uint64_t make_desc(uint32_t addr) {
    return (uint64_t(2) << 61) | (uint64_t(1) << 46) | (uint64_t(64) << 32) |
           (uint64_t(1) << 16) | ((uint64_t)(addr >> 4) & 0x3FFF);
}

#define MBAR_INIT(a, c) asm volatile("mbarrier.init.shared.b64 [%0], %1;" :: "r"(a), "r"(c) : "memory")
#define MBAR_INVAL(a)   asm volatile("mbarrier.inval.shared.b64 [%0];" :: "r"(a) : "memory")
#define MBAR_WAIT(a, ph) do {                                                     \
    uint32_t _m = (a), _p = (ph), _d;                                             \
    asm volatile("{ .reg .pred p; mbarrier.try_wait.parity.acquire.cta.shared::cta.b64 p, [%1], %2; selp.b32 %0,1,0,p; }" \
                 : "=r"(_d) : "r"(_m), "r"(_p) : "memory");                       \
    if (!_d) {                                                                    \
        asm volatile("{ .reg .pred P1; WL%=: mbarrier.try_wait.parity.acquire.cta.shared::cta.b64 P1, [%0], %1, 0x989680;" \
                     " @P1 bra.uni WD%=; bra.uni WL%=; WD%=: }"                   \
                     :: "r"(_m), "r"(_p) : "memory");                             \
    } } while (0)

#if HAS_TCGEN05
#define TC_ALLOC(sa, n)   asm volatile("tcgen05.alloc.cta_group::1.sync.aligned.shared::cta.b32 [%0], %1;" :: "r"(sa), "r"(n) : "memory")
#define TC_DEALLOC(t, n)  asm volatile("tcgen05.dealloc.cta_group::1.sync.aligned.b32 %0, %1;" :: "r"(t), "r"(n))
#define TC_RELINQ()       asm volatile("tcgen05.relinquish_alloc_permit.cta_group::1.sync.aligned;")
#define TC_COMMIT(mb)     asm volatile("tcgen05.commit.cta_group::1.mbarrier::arrive::one.shared::cluster.b64 [%0];" :: "r"(mb) : "memory")
#define TC_WAIT_LD()      asm volatile("tcgen05.wait::ld.sync.aligned;" ::: "memory")
#define TC_WAIT_ST()      asm volatile("tcgen05.wait::st.sync.aligned;" ::: "memory")
#define TC_FENCE_BEFORE() asm volatile("tcgen05.fence::before_thread_sync;" ::: "memory")
#define TC_FENCE_AFTER()  asm volatile("tcgen05.fence::after_thread_sync;" ::: "memory")
#define FENCE_ASYNC()     asm volatile("fence.proxy.async.shared::cta;" ::: "memory")

#define LDTM_X32(r, a)                                                              \
    asm volatile("tcgen05.ld.sync.aligned.32x32b.x32.b32 "                          \
        "{%0,%1,%2,%3,%4,%5,%6,%7,%8,%9,%10,%11,%12,%13,%14,%15,"                   \
        "%16,%17,%18,%19,%20,%21,%22,%23,%24,%25,%26,%27,%28,%29,%30,%31}, [%32];"  \
        : "=r"((r)[0]),"=r"((r)[1]),"=r"((r)[2]),"=r"((r)[3]),"=r"((r)[4]),"=r"((r)[5]),"=r"((r)[6]),"=r"((r)[7]), \
          "=r"((r)[8]),"=r"((r)[9]),"=r"((r)[10]),"=r"((r)[11]),"=r"((r)[12]),"=r"((r)[13]),"=r"((r)[14]),"=r"((r)[15]), \
          "=r"((r)[16]),"=r"((r)[17]),"=r"((r)[18]),"=r"((r)[19]),"=r"((r)[20]),"=r"((r)[21]),"=r"((r)[22]),"=r"((r)[23]), \
          "=r"((r)[24]),"=r"((r)[25]),"=r"((r)[26]),"=r"((r)[27]),"=r"((r)[28]),"=r"((r)[29]),"=r"((r)[30]),"=r"((r)[31]) \
        : "r"(a))

#define STTM_X32(a, r)                                                              \
    asm volatile("tcgen05.st.sync.aligned.32x32b.x32.b32 [%0], "                    \
        "{%1,%2,%3,%4,%5,%6,%7,%8,%9,%10,%11,%12,%13,%14,%15,%16,"                  \
        "%17,%18,%19,%20,%21,%22,%23,%24,%25,%26,%27,%28,%29,%30,%31,%32};"         \
        :: "r"(a),                                                                  \
           "r"((r)[0]),"r"((r)[1]),"r"((r)[2]),"r"((r)[3]),"r"((r)[4]),"r"((r)[5]),"r"((r)[6]),"r"((r)[7]), \
           "r"((r)[8]),"r"((r)[9]),"r"((r)[10]),"r"((r)[11]),"r"((r)[12]),"r"((r)[13]),"r"((r)[14]),"r"((r)[15]), \
           "r"((r)[16]),"r"((r)[17]),"r"((r)[18]),"r"((r)[19]),"r"((r)[20]),"r"((r)[21]),"r"((r)[22]),"r"((r)[23]), \
           "r"((r)[24]),"r"((r)[25]),"r"((r)[26]),"r"((r)[27]),"r"((r)[28]),"r"((r)[29]),"r"((r)[30]),"r"((r)[31]) \
        : "memory")

__device__ __forceinline__ void mma_tf32_ss(uint32_t d, uint64_t a, uint64_t b,
                                            uint32_t idesc, bool acc) {
    uint32_t e = acc ? 1u : 0u;
    asm volatile("{ .reg .pred p; setp.ne.u32 p, %4, 0;"
                 " tcgen05.mma.cta_group::1.kind::tf32 [%0], %1, %2, %3, p; }"
                 :: "r"(d), "l"(a), "l"(b), "r"(idesc), "r"(e) : "memory");
}
__device__ __forceinline__ void mma_tf32_ts(uint32_t d, uint32_t a, uint64_t b,
                                            uint32_t idesc, bool acc) {
    uint32_t e = acc ? 1u : 0u;
    asm volatile("{ .reg .pred p; setp.ne.u32 p, %4, 0;"
                 " tcgen05.mma.cta_group::1.kind::tf32 [%0], [%1], %2, %3, p; }"
                 :: "r"(d), "r"(a), "l"(b), "r"(idesc), "r"(e) : "memory");
}
#endif

__global__ void detect_kernel(const int* __restrict__ ei32) {
    int any = 0;
    #pragma unroll
    for (int i = 0; i < 64; i++) any |= ei32[2 * i + 1];
    g_idx_is64 = (any == 0) ? 1 : 0;
}

__global__ void prep_w_kernel(const float* __restrict__ W1,
                              const float* __restrict__ W2) {
    int idx = blockIdx.x * blockDim.x + threadIdx.x;
    if (idx >= DIM * HID) return;
    {
        int j = idx & 127, k = idx >> 7;
        uint32_t byte = ((j >> 3) + (k >> 5) * 16) * 1024 + (j & 7) * 128 + (k & 31) * 4;
        g_w1t[sw128(byte) >> 2] = cvt_tf32(W1[k * HID + j]);
    }
    {
        int d = idx & 63, k = idx >> 6;
        uint32_t byte = ((d >> 3) + (k >> 5) * 8) * 1024 + (d & 7) * 128 + (k & 31) * 4;
        g_w2t[sw128(byte) >> 2] = cvt_tf32(W2[k * DIM + d]);
    }
}

__global__ void zero_kernel(float4* __restrict__ out) {
    int i = blockIdx.x * blockDim.x + threadIdx.x;
    if (i < N_NODES * DIM / 4) out[i] = make_float4(0.f, 0.f, 0.f, 0.f);
}

__global__ void scatter_kernel(const float* __restrict__ x,
                               const void* __restrict__ ei_raw,
                               float* __restrict__ out) {
    int i = blockIdx.x * blockDim.x + threadIdx.x;
    if (i >= N_EDGES * (DIM / 4)) return;
    int e = i >> 4;
    int c = i & 15;
    unsigned int s, d;
    if (g_idx_is64) {
        const long long* ei = (const long long*)ei_raw;
        s = (unsigned int)ei[e];
        d = (unsigned int)ei[N_EDGES + e];
    } else {
        const int* ei = (const int*)ei_raw;
        s = (unsigned int)ei[e];
        d = (unsigned int)ei[N_EDGES + e];
    }
    if (s >= N_NODES || d >= N_NODES) return;
    float4 v = __ldg(((const float4*)(x + (size_t)s * DIM)) + c);
    float* p = out + (size_t)d * DIM + c * 4;
    asm volatile("red.global.add.v4.f32 [%0], {%1, %2, %3, %4};"
                 :: "l"(p), "f"(v.x), "f"(v.y), "f"(v.z), "f"(v.w)
                 : "memory");
}

#define SM_TMEM  0
#define SM_MBAR  8
#define SM_X     1024
#define SM_W1    (SM_X + 32768)
#define SM_W2    (SM_W1 + 32768)
#define SM_B1    (SM_W2 + 32768)
#define SM_B2    (SM_B1 + 512)
#define SM_TOTAL (SM_B2 + 512)

#define T_D1   0
#define T_A2   128
#define T_D2   0
#define T_COLS 256

#define IDESC1 ((1u << 4) | (2u << 7) | (2u << 10) | ((HID / 8) << 17) | ((TILE_M / 16) << 24))
#define IDESC2 ((1u << 4) | (2u << 7) | (2u << 10) | ((DIM / 8) << 17) | ((TILE_M / 16) << 24))

__global__ __launch_bounds__(256, 2)
void mlp_tc_kernel(float* __restrict__ buf, const float* __restrict__ x,
                   const float* __restrict__ b1, const float* __restrict__ b2) {
#if HAS_TCGEN05
    extern __shared__ char smem[];
    uint32_t sb = smem_u32(smem);
    int tid = threadIdx.x;
    int wid = tid >> 5;
    int lid = tid & 31;
    int wg  = wid >> 2;
    uint32_t woff = (uint32_t)(wid & 3) << 21;

    if (wid == 0) {
        TC_ALLOC(sb + SM_TMEM, T_COLS);
        TC_RELINQ();
        if (elect_one()) MBAR_INIT(sb + SM_MBAR, 1);
    }
    __syncthreads();
    uint32_t tmem;
    asm volatile("ld.shared.b32 %0, [%1];" : "=r"(tmem) : "r"(sb + SM_TMEM));

    {
        const uint4* s1 = (const uint4*)g_w1t;
        const uint4* s2 = (const uint4*)g_w2t;
        uint4* d1 = (uint4*)(smem + SM_W1);
        uint4* d2 = (uint4*)(smem + SM_W2);
        for (int i = tid; i < DIM * HID / 4; i += 256) {
            d1[i] = __ldg(s1 + i);
            d2[i] = __ldg(s2 + i);
        }
    }
    if (tid < HID) ((float*)(smem + SM_B1))[tid] = b1[tid];
    if (tid < DIM) ((float*)(smem + SM_B2))[tid] = b2[tid];

    int ph = 0;
    #pragma unroll 1
    for (int t = 0; t < TILES_PER_CTA; t++) {
        int tile = blockIdx.x * TILES_PER_CTA + t;
        if (tile >= NT) break;
        int base = tile * TILE_M;

        __syncthreads();

        for (int i = tid; i < TILE_M * (DIM / 4); i += 256) {
            int row = i >> 4;
            int c4  = i & 15;
            int node = base + row;
            float4 s = make_float4(0.f, 0.f, 0.f, 0.f);
            if (node < N_NODES) {
                float4 a = __ldg(((const float4*)(buf + (size_t)node * DIM)) + c4);
                float4 b = __ldg(((const float4*)(x + (size_t)node * DIM)) + c4);
                s = make_float4(a.x + b.x, a.y + b.y, a.z + b.z, a.w + b.w);
            }
            uint32_t byte = ((row >> 3) + (c4 >> 3) * 16) * 1024 + (row & 7) * 128 + (c4 & 7) * 16;
            *(uint4*)(smem + SM_X + sw128(byte)) =
                make_uint4(cvt_tf32(s.x), cvt_tf32(s.y), cvt_tf32(s.z), cvt_tf32(s.w));
        }
        FENCE_ASYNC();
        __syncthreads();

        if (wid == 0) {
            TC_FENCE_AFTER();
            if (elect_one()) {
                uint64_t ad = make_desc(sb + SM_X);
                uint64_t bd = make_desc(sb + SM_W1);
                #pragma unroll
                for (int s = 0; s < 8; s++) {
                    uint64_t off = (uint64_t)((s >> 2) * 1024 + (s & 3) * 2);
                    mma_tf32_ss(tmem + T_D1, ad + off, bd + off, IDESC1, s > 0);
                }
                TC_COMMIT(sb + SM_MBAR);
            }
        }
        MBAR_WAIT(sb + SM_MBAR, ph); ph ^= 1;
        TC_FENCE_AFTER();

        {
            const float* b1s = (const float*)(smem + SM_B1);
            #pragma unroll
            for (int blk = 0; blk < 2; blk++) {
                int c0 = wg * 64 + blk * 32;
                uint32_t r[32];
                LDTM_X32(r, tmem + woff + T_D1 + c0);
                TC_WAIT_LD();
                #pragma unroll
                for (int i = 0; i < 32; i++) {
                    float f = __uint_as_float(r[i]) + b1s[c0 + i];
                    r[i] = cvt_tf32(fmaxf(f, 0.f));
                }
                STTM_X32(tmem + woff + T_A2 + c0, r);
            }
            TC_WAIT_ST();
        }
        TC_FENCE_BEFORE();
        __syncthreads();

        if (wid == 0) {
            TC_FENCE_AFTER();
            if (elect_one()) {
                uint64_t bd = make_desc(sb + SM_W2);
                #pragma unroll
                for (int s = 0; s < 16; s++) {
                    uint64_t off = (uint64_t)((s >> 2) * 512 + (s & 3) * 2);
                    mma_tf32_ts(tmem + T_D2, tmem + T_A2 + s * 8, bd + off, IDESC2, s > 0);
                }
                TC_COMMIT(sb + SM_MBAR);
            }
        }
        MBAR_WAIT(sb + SM_MBAR, ph); ph ^= 1;
        TC_FENCE_AFTER();

        {
            const float* b2s = (const float*)(smem + SM_B2);
            int node = base + (wid & 3) * 32 + lid;
            int c0 = wg * 32;
            uint32_t r[32];
            LDTM_X32(r, tmem + woff + T_D2 + c0);
            TC_WAIT_LD();
            if (node < N_NODES) {
                float* op = buf + (size_t)node * DIM + c0;
                #pragma unroll
                for (int g = 0; g < 8; g++) {
                    float4 v;
                    v.x = __uint_as_float(r[4 * g + 0]) + b2s[c0 + 4 * g + 0];
                    v.y = __uint_as_float(r[4 * g + 1]) + b2s[c0 + 4 * g + 1];
                    v.z = __uint_as_float(r[4 * g + 2]) + b2s[c0 + 4 * g + 2];
                    v.w = __uint_as_float(r[4 * g + 3]) + b2s[c0 + 4 * g + 3];
                    *(float4*)(op + 4 * g) = v;
                }
            }
        }
        TC_FENCE_BEFORE();
    }

    __syncthreads();
    if (wid == 0) {
        if (elect_one()) MBAR_INVAL(sb + SM_MBAR);
        TC_DEALLOC(tmem, T_COLS);
    }
#endif
}

extern "C" void kernel_launch(void* const* d_in, const int* in_sizes, int n_in,
                              void* d_out, int out_size) {
    const float* x  = (const float*)d_in[0];
    const void*  ei = d_in[1];
    const float* W1 = (const float*)d_in[2];
    const float* b1 = (const float*)d_in[3];
    const float* W2 = (const float*)d_in[4];
    const float* b2 = (const float*)d_in[5];
    float* out = (float*)d_out;

    cudaFuncSetAttribute(mlp_tc_kernel, cudaFuncAttributeMaxDynamicSharedMemorySize,
                         SM_TOTAL);

    detect_kernel<<<1, 1>>>((const int*)ei);
    prep_w_kernel<<<(DIM * HID + 255) / 256, 256>>>(W1, W2);
    {
        int n = N_NODES * DIM / 4;
        zero_kernel<<<(n + 255) / 256, 256>>>((float4*)out);
    }
    {
        int n = N_EDGES * (DIM / 4);
        scatter_kernel<<<(n + 255) / 256, 256>>>(x, ei, out);
    }
    mlp_tc_kernel<<<MLP_GRID, 256, SM_TOTAL>>>(out, x, b1, b2);
}